// round 1
// baseline (speedup 1.0000x reference)
#include <cuda_runtime.h>

#define Bb  4
#define Ss  2048
#define Dd  1024
#define Hh  16
#define DHh 64
#define BH  (Bb*Hh)   // 64
#define BSz (Bb*Ss)   // 8192

// Scratch (allocation-free rule: __device__ globals)
__device__ float g_Qh[(size_t)BH * Ss * DHh];
__device__ float g_Kh[(size_t)BH * Ss * DHh];
__device__ float g_Vh[(size_t)BH * Ss * DHh];
__device__ float g_ctx[(size_t)BSz * Dd];

// ---------------------------------------------------------------------------
// Generic fp32 SGEMM: Y = X[M,K] @ W[K,N] + bias[N]
// SPLIT=1: write Y in head-split layout [B,H,S,dh]; SPLIT=0: row-major [M,N]
// Tile 128x128xBK=8, 256 threads, 8x8 per thread.
// ---------------------------------------------------------------------------
template <int SPLIT>
__global__ void __launch_bounds__(256)
sgemm_bias_k(const float* __restrict__ X, const float* __restrict__ W,
             const float* __restrict__ bias, float* __restrict__ Y,
             int M, int N, int K)
{
    __shared__ float As[8][128];
    __shared__ float Bs[8][128];

    const int tid = threadIdx.x;
    const int bm  = blockIdx.y * 128;
    const int bn  = blockIdx.x * 128;
    const int tx  = tid & 15;
    const int ty  = tid >> 4;

    const int arow = tid >> 1;         // 0..127
    const int acol = (tid & 1) * 4;    // 0 or 4
    const int brow = tid >> 5;         // 0..7
    const int bcol = (tid & 31) * 4;   // 0..124

    float acc[8][8];
#pragma unroll
    for (int i = 0; i < 8; i++)
#pragma unroll
        for (int j = 0; j < 8; j++) acc[i][j] = 0.f;

    for (int k0 = 0; k0 < K; k0 += 8) {
        float4 a4 = *(const float4*)(X + (size_t)(bm + arow) * K + k0 + acol);
        As[acol + 0][arow] = a4.x;
        As[acol + 1][arow] = a4.y;
        As[acol + 2][arow] = a4.z;
        As[acol + 3][arow] = a4.w;
        float4 b4 = *(const float4*)(W + (size_t)(k0 + brow) * N + bn + bcol);
        *(float4*)&Bs[brow][bcol] = b4;
        __syncthreads();

#pragma unroll
        for (int k = 0; k < 8; k++) {
            float a[8], bb[8];
            *(float4*)&a[0]  = *(float4*)&As[k][ty * 8];
            *(float4*)&a[4]  = *(float4*)&As[k][ty * 8 + 4];
            *(float4*)&bb[0] = *(float4*)&Bs[k][tx * 8];
            *(float4*)&bb[4] = *(float4*)&Bs[k][tx * 8 + 4];
#pragma unroll
            for (int i = 0; i < 8; i++)
#pragma unroll
                for (int j = 0; j < 8; j++)
                    acc[i][j] += a[i] * bb[j];
        }
        __syncthreads();
    }

    float bv[8];
#pragma unroll
    for (int j = 0; j < 8; j++) bv[j] = bias[bn + tx * 8 + j];

#pragma unroll
    for (int i = 0; i < 8; i++) {
        const int m = bm + ty * 8 + i;
        const int n = bn + tx * 8;
        float r[8];
#pragma unroll
        for (int j = 0; j < 8; j++) r[j] = acc[i][j] + bv[j];
        if (SPLIT) {
            const int bidx = m / Ss;
            const int s    = m % Ss;
            const int h    = n / DHh;
            const int dc   = n % DHh;   // 8 cols stay inside one head (8 | 64)
            float* dst = Y + (((size_t)bidx * Hh + h) * Ss + s) * DHh + dc;
            *(float4*)(dst)     = make_float4(r[0], r[1], r[2], r[3]);
            *(float4*)(dst + 4) = make_float4(r[4], r[5], r[6], r[7]);
        } else {
            float* dst = Y + (size_t)m * N + n;
            *(float4*)(dst)     = make_float4(r[0], r[1], r[2], r[3]);
            *(float4*)(dst + 4) = make_float4(r[4], r[5], r[6], r[7]);
        }
    }
}

// ---------------------------------------------------------------------------
// logits[bh, m, n] = 0.125 * sum_d Q[bh,m,d]*K[bh,n,d]  + mask[b,n]*(-1e9)
// per (b,h): 2048x2048x64 NT gemm; 128x128 tile, BK=32 (2 iters), 8x8/thread
// ---------------------------------------------------------------------------
__global__ void __launch_bounds__(256)
logits_k(const float* __restrict__ Qh, const float* __restrict__ Kh,
         const float* __restrict__ mask, float* __restrict__ attn)
{
    const int bh = blockIdx.z;
    const int b  = bh >> 4;
    const float* Q  = Qh + (size_t)bh * Ss * DHh;
    const float* Kp = Kh + (size_t)bh * Ss * DHh;
    const int bm = blockIdx.y * 128;
    const int bn = blockIdx.x * 128;

    __shared__ float Qs[32][132];
    __shared__ float Ks[32][132];

    const int tid = threadIdx.x;
    const int tx  = tid & 15;
    const int ty  = tid >> 4;
    const int lr  = tid >> 3;        // 0..31
    const int lc  = (tid & 7) * 4;   // 0..28

    float acc[8][8] = {};

    for (int k0 = 0; k0 < DHh; k0 += 32) {
#pragma unroll
        for (int p = 0; p < 4; p++) {
            const int m = lr + p * 32;
            float4 q4 = *(const float4*)(Q + (size_t)(bm + m) * DHh + k0 + lc);
            Qs[lc + 0][m] = q4.x; Qs[lc + 1][m] = q4.y;
            Qs[lc + 2][m] = q4.z; Qs[lc + 3][m] = q4.w;
            float4 k4 = *(const float4*)(Kp + (size_t)(bn + m) * DHh + k0 + lc);
            Ks[lc + 0][m] = k4.x; Ks[lc + 1][m] = k4.y;
            Ks[lc + 2][m] = k4.z; Ks[lc + 3][m] = k4.w;
        }
        __syncthreads();

#pragma unroll
        for (int k = 0; k < 32; k++) {
            float a[8], bb[8];
            *(float4*)&a[0]  = *(float4*)&Qs[k][ty * 8];
            *(float4*)&a[4]  = *(float4*)&Qs[k][ty * 8 + 4];
            *(float4*)&bb[0] = *(float4*)&Ks[k][tx * 8];
            *(float4*)&bb[4] = *(float4*)&Ks[k][tx * 8 + 4];
#pragma unroll
            for (int i = 0; i < 8; i++)
#pragma unroll
                for (int j = 0; j < 8; j++)
                    acc[i][j] += a[i] * bb[j];
        }
        __syncthreads();
    }

    float mk[8];
#pragma unroll
    for (int j = 0; j < 8; j++)
        mk[j] = mask[(size_t)b * Ss + bn + tx * 8 + j] * -1e9f;

#pragma unroll
    for (int i = 0; i < 8; i++) {
        const int m = bm + ty * 8 + i;
        float r[8];
#pragma unroll
        for (int j = 0; j < 8; j++) r[j] = acc[i][j] * 0.125f + mk[j];
        float* dst = attn + ((size_t)bh * Ss + m) * Ss + bn + tx * 8;
        *(float4*)(dst)     = make_float4(r[0], r[1], r[2], r[3]);
        *(float4*)(dst + 4) = make_float4(r[4], r[5], r[6], r[7]);
    }
}

// ---------------------------------------------------------------------------
// In-place row softmax over rows of length 2048. One CTA (256 thr) per row.
// ---------------------------------------------------------------------------
__global__ void __launch_bounds__(256)
softmax_k(float* __restrict__ attn)
{
    float* p = attn + (size_t)blockIdx.x * Ss;
    const int tid = threadIdx.x;

    float4 v0 = *(float4*)(p + tid * 4);
    float4 v1 = *(float4*)(p + 1024 + tid * 4);

    float mx = fmaxf(fmaxf(fmaxf(v0.x, v0.y), fmaxf(v0.z, v0.w)),
                     fmaxf(fmaxf(v1.x, v1.y), fmaxf(v1.z, v1.w)));

    __shared__ float red[256];
    red[tid] = mx;
    __syncthreads();
#pragma unroll
    for (int s = 128; s > 0; s >>= 1) {
        if (tid < s) red[tid] = fmaxf(red[tid], red[tid + s]);
        __syncthreads();
    }
    mx = red[0];
    __syncthreads();

    float e[8];
    e[0] = __expf(v0.x - mx); e[1] = __expf(v0.y - mx);
    e[2] = __expf(v0.z - mx); e[3] = __expf(v0.w - mx);
    e[4] = __expf(v1.x - mx); e[5] = __expf(v1.y - mx);
    e[6] = __expf(v1.z - mx); e[7] = __expf(v1.w - mx);

    float sum = ((e[0] + e[1]) + (e[2] + e[3])) + ((e[4] + e[5]) + (e[6] + e[7]));
    red[tid] = sum;
    __syncthreads();
#pragma unroll
    for (int s = 128; s > 0; s >>= 1) {
        if (tid < s) red[tid] += red[tid + s];
        __syncthreads();
    }
    const float inv = 1.0f / red[0];

    *(float4*)(p + tid * 4)        = make_float4(e[0] * inv, e[1] * inv, e[2] * inv, e[3] * inv);
    *(float4*)(p + 1024 + tid * 4) = make_float4(e[4] * inv, e[5] * inv, e[6] * inv, e[7] * inv);
}

// ---------------------------------------------------------------------------
// ctx[b, s, h*64+dc] = sum_k attn[bh,s,k] * Vh[bh,k,dc]
// per (b,h): 2048x64x2048; tile 128x64, BK=16; 256 thr, 8x4 per thread.
// Writes head-concat layout [B,S,D] directly.
// ---------------------------------------------------------------------------
__global__ void __launch_bounds__(256)
ctx_k(const float* __restrict__ attn, const float* __restrict__ Vh,
      float* __restrict__ ctx)
{
    const int bh = blockIdx.z;
    const int b  = bh >> 4;
    const int h  = bh & 15;
    const float* A = attn + (size_t)bh * Ss * Ss;
    const float* V = Vh   + (size_t)bh * Ss * DHh;
    const int bm = blockIdx.x * 128;

    __shared__ float As[16][132];
    __shared__ float Vs[16][64];

    const int tid = threadIdx.x;
    const int tx  = tid & 15;
    const int ty  = tid >> 4;
    const int am  = tid >> 2;         // 0..63
    const int ak  = (tid & 3) * 4;    // 0..12
    const int vk  = tid >> 4;         // 0..15
    const int vn  = (tid & 15) * 4;   // 0..60

    float acc[8][4] = {};

    for (int k0 = 0; k0 < Ss; k0 += 16) {
#pragma unroll
        for (int p = 0; p < 2; p++) {
            const int m = am + p * 64;
            float4 a4 = *(const float4*)(A + (size_t)(bm + m) * Ss + k0 + ak);
            As[ak + 0][m] = a4.x; As[ak + 1][m] = a4.y;
            As[ak + 2][m] = a4.z; As[ak + 3][m] = a4.w;
        }
        *(float4*)&Vs[vk][vn] =
            *(const float4*)(V + (size_t)(k0 + vk) * DHh + vn);
        __syncthreads();

#pragma unroll
        for (int k = 0; k < 16; k++) {
            float a[8];
            *(float4*)&a[0] = *(float4*)&As[k][ty * 8];
            *(float4*)&a[4] = *(float4*)&As[k][ty * 8 + 4];
            float4 bb = *(float4*)&Vs[k][tx * 4];
#pragma unroll
            for (int i = 0; i < 8; i++) {
                acc[i][0] += a[i] * bb.x;
                acc[i][1] += a[i] * bb.y;
                acc[i][2] += a[i] * bb.z;
                acc[i][3] += a[i] * bb.w;
            }
        }
        __syncthreads();
    }

#pragma unroll
    for (int i = 0; i < 8; i++) {
        const int s = bm + ty * 8 + i;
        float* dst = ctx + ((size_t)b * Ss + s) * Dd + h * DHh + tx * 4;
        *(float4*)dst = make_float4(acc[i][0], acc[i][1], acc[i][2], acc[i][3]);
    }
}

// ---------------------------------------------------------------------------
extern "C" void kernel_launch(void* const* d_in, const int* in_sizes, int n_in,
                              void* d_out, int out_size)
{
    const float* q    = (const float*)d_in[0];
    const float* k    = (const float*)d_in[1];
    const float* v    = (const float*)d_in[2];
    const float* mask = (const float*)d_in[3];
    const float* Wq   = (const float*)d_in[4];
    const float* bq   = (const float*)d_in[5];
    const float* Wk   = (const float*)d_in[6];
    const float* bk   = (const float*)d_in[7];
    const float* Wv   = (const float*)d_in[8];
    const float* bv   = (const float*)d_in[9];
    const float* Wo   = (const float*)d_in[10];
    const float* bo   = (const float*)d_in[11];

    float* out  = (float*)d_out;
    float* attn = out + (size_t)BSz * Dd;   // tuple order: (out, attn)

    float *Qh, *Kh, *Vh, *ctx;
    cudaGetSymbolAddress((void**)&Qh,  g_Qh);
    cudaGetSymbolAddress((void**)&Kh,  g_Kh);
    cudaGetSymbolAddress((void**)&Vh,  g_Vh);
    cudaGetSymbolAddress((void**)&ctx, g_ctx);

    const dim3 gProj(Dd / 128, BSz / 128);        // (8, 64)

    sgemm_bias_k<1><<<gProj, 256>>>(q, Wq, bq, Qh, BSz, Dd, Dd);
    sgemm_bias_k<1><<<gProj, 256>>>(k, Wk, bk, Kh, BSz, Dd, Dd);
    sgemm_bias_k<1><<<gProj, 256>>>(v, Wv, bv, Vh, BSz, Dd, Dd);

    logits_k<<<dim3(Ss / 128, Ss / 128, BH), 256>>>(Qh, Kh, mask, attn);

    softmax_k<<<dim3(BH * Ss), 256>>>(attn);

    ctx_k<<<dim3(Ss / 128, 1, BH), 256>>>(attn, Vh, ctx);

    sgemm_bias_k<0><<<gProj, 256>>>(ctx, Wo, bo, out, BSz, Dd, Dd);
}

// round 2
// speedup vs baseline: 1.0687x; 1.0687x over previous
#include <cuda_runtime.h>
#include <cstdint>

#define Bb  4
#define Ss  2048
#define Dd  1024
#define Hh  16
#define DHh 64
#define BH  (Bb*Hh)   // 64
#define BSz (Bb*Ss)   // 8192

// Scratch (allocation-free rule: __device__ globals)
__device__ float g_Qh[(size_t)BH * Ss * DHh];
__device__ float g_Kh[(size_t)BH * Ss * DHh];
__device__ float g_Vh[(size_t)BH * Ss * DHh];
__device__ float g_ctx[(size_t)BSz * Dd];
__device__ float g_rowsum[(size_t)BH * Ss];

// ---------------------------------------------------------------------------
__device__ __forceinline__ void cp16(void* dst, const void* src) {
    uint32_t d;
    asm volatile("{ .reg .u64 t; cvta.to.shared.u64 t, %1; cvt.u32.u64 %0, t; }"
                 : "=r"(d) : "l"(dst));
    asm volatile("cp.async.cg.shared.global [%0], [%1], 16;" :: "r"(d), "l"(src));
}
#define CP_COMMIT() asm volatile("cp.async.commit_group;")
#define CP_WAIT(n)  asm volatile("cp.async.wait_group %0;" :: "n"(n))

__global__ void zero_k(float* p, int n) {
    int i = blockIdx.x * 256 + threadIdx.x;
    if (i < n) p[i] = 0.f;
}

// ---------------------------------------------------------------------------
// Fused projection GEMM: Y = X[8192,1024] @ W[1024,1024] + bias
// blockIdx.z selects (X,W,b,Y) set. SPLIT=1: head-split output layout.
// 128x128 tile, BK=16, 256 thr, 8x8/thread, cp.async double buffer,
// XOR-swizzled A tile (row-major [row][16]).
// ---------------------------------------------------------------------------
template <int SPLIT>
__global__ void __launch_bounds__(256)
gemm_k(const float* __restrict__ X0, const float* __restrict__ X1,
       const float* __restrict__ X2,
       const float* __restrict__ W0, const float* __restrict__ W1,
       const float* __restrict__ W2,
       const float* __restrict__ B0, const float* __restrict__ B1,
       const float* __restrict__ B2,
       float* __restrict__ Y0, float* __restrict__ Y1, float* __restrict__ Y2)
{
    const float* X = blockIdx.z == 0 ? X0 : blockIdx.z == 1 ? X1 : X2;
    const float* W = blockIdx.z == 0 ? W0 : blockIdx.z == 1 ? W1 : W2;
    const float* Bi = blockIdx.z == 0 ? B0 : blockIdx.z == 1 ? B1 : B2;
    float* Y = blockIdx.z == 0 ? Y0 : blockIdx.z == 1 ? Y1 : Y2;

    __shared__ float As[2][128][16];
    __shared__ float Bs[2][16][128];

    const int tid = threadIdx.x;
    const int bm = blockIdx.y * 128;
    const int bn = blockIdx.x * 128;
    const int tx = tid & 15;
    const int ty = tid >> 4;

    // A loader: rows lr, lr+64; 16B chunk lc; swizzle slot
    const int lr = tid >> 2;
    const int lc = tid & 3;
    const int sw = (lc ^ ((lr >> 3) & 3)) * 4;   // same for lr and lr+64
    // B loader: rows kr, kr+8; 16B chunk col
    const int kr = tid >> 5;
    const int bc = (tid & 31) * 4;

    float acc[8][8] = {};

    // prologue
    cp16(&As[0][lr][sw],      X + (size_t)(bm + lr) * 1024 + lc * 4);
    cp16(&As[0][lr + 64][sw], X + (size_t)(bm + lr + 64) * 1024 + lc * 4);
    cp16(&Bs[0][kr][bc],      W + (size_t)kr * 1024 + bn + bc);
    cp16(&Bs[0][kr + 8][bc],  W + (size_t)(kr + 8) * 1024 + bn + bc);
    CP_COMMIT();

    for (int it = 0; it < 64; ++it) {
        const int s = it & 1;
        if (it + 1 < 64) {
            const int k0 = (it + 1) * 16;
            cp16(&As[s ^ 1][lr][sw],      X + (size_t)(bm + lr) * 1024 + k0 + lc * 4);
            cp16(&As[s ^ 1][lr + 64][sw], X + (size_t)(bm + lr + 64) * 1024 + k0 + lc * 4);
            cp16(&Bs[s ^ 1][kr][bc],      W + (size_t)(k0 + kr) * 1024 + bn + bc);
            cp16(&Bs[s ^ 1][kr + 8][bc],  W + (size_t)(k0 + kr + 8) * 1024 + bn + bc);
            CP_COMMIT();
            CP_WAIT(1);
        } else {
            CP_WAIT(0);
        }
        __syncthreads();

#pragma unroll
        for (int k4 = 0; k4 < 4; k4++) {
            float4 a4[8];
            const int sa = (k4 ^ (ty & 3)) * 4;
#pragma unroll
            for (int i = 0; i < 8; i++)
                a4[i] = *(const float4*)&As[s][ty * 8 + i][sa];
#pragma unroll
            for (int kk = 0; kk < 4; kk++) {
                float b[8];
                *(float4*)&b[0] = *(const float4*)&Bs[s][k4 * 4 + kk][tx * 8];
                *(float4*)&b[4] = *(const float4*)&Bs[s][k4 * 4 + kk][tx * 8 + 4];
#pragma unroll
                for (int i = 0; i < 8; i++) {
                    const float av = kk == 0 ? a4[i].x : kk == 1 ? a4[i].y
                                   : kk == 2 ? a4[i].z : a4[i].w;
#pragma unroll
                    for (int j = 0; j < 8; j++)
                        acc[i][j] = fmaf(av, b[j], acc[i][j]);
                }
            }
        }
        __syncthreads();
    }

    float bv[8];
#pragma unroll
    for (int j = 0; j < 8; j++) bv[j] = Bi[bn + tx * 8 + j];

#pragma unroll
    for (int i = 0; i < 8; i++) {
        const int m = bm + ty * 8 + i;
        const int n = bn + tx * 8;
        float r[8];
#pragma unroll
        for (int j = 0; j < 8; j++) r[j] = acc[i][j] + bv[j];
        if (SPLIT) {
            const int bidx = m / Ss;
            const int srow = m % Ss;
            const int h    = n / DHh;
            const int dc   = n % DHh;
            float* dst = Y + (((size_t)bidx * Hh + h) * Ss + srow) * DHh + dc;
            *(float4*)(dst)     = make_float4(r[0], r[1], r[2], r[3]);
            *(float4*)(dst + 4) = make_float4(r[4], r[5], r[6], r[7]);
        } else {
            float* dst = Y + (size_t)m * 1024 + n;
            *(float4*)(dst)     = make_float4(r[0], r[1], r[2], r[3]);
            *(float4*)(dst + 4) = make_float4(r[4], r[5], r[6], r[7]);
        }
    }
}

// ---------------------------------------------------------------------------
// logits+exp: e[bh,m,n] = exp(0.125*Q·K + mask*(-1e9)); rowsum += partial sums
// 128x128 tile per (bh); K=64, BK=16 double-buffered.
// ---------------------------------------------------------------------------
__global__ void __launch_bounds__(256)
logits_k(const float* __restrict__ Qh, const float* __restrict__ Kh,
         const float* __restrict__ mask, float* __restrict__ attn,
         float* __restrict__ rowsum)
{
    const int bh = blockIdx.z;
    const int b  = bh >> 4;
    const float* Q  = Qh + (size_t)bh * Ss * DHh;
    const float* Kp = Kh + (size_t)bh * Ss * DHh;
    const int bm = blockIdx.y * 128;
    const int bn = blockIdx.x * 128;

    __shared__ float Qs[2][128][16];
    __shared__ float Ks[2][128][16];
    __shared__ float red[128][17];

    const int tid = threadIdx.x;
    const int tx = tid & 15;
    const int ty = tid >> 4;
    const int lr = tid >> 2;
    const int lc = tid & 3;
    const int sw = (lc ^ ((lr >> 3) & 3)) * 4;

    float acc[8][8] = {};

    cp16(&Qs[0][lr][sw],      Q + (size_t)(bm + lr) * DHh + lc * 4);
    cp16(&Qs[0][lr + 64][sw], Q + (size_t)(bm + lr + 64) * DHh + lc * 4);
    cp16(&Ks[0][lr][sw],      Kp + (size_t)(bn + lr) * DHh + lc * 4);
    cp16(&Ks[0][lr + 64][sw], Kp + (size_t)(bn + lr + 64) * DHh + lc * 4);
    CP_COMMIT();

    for (int it = 0; it < 4; ++it) {
        const int s = it & 1;
        if (it + 1 < 4) {
            const int k0 = (it + 1) * 16;
            cp16(&Qs[s ^ 1][lr][sw],      Q + (size_t)(bm + lr) * DHh + k0 + lc * 4);
            cp16(&Qs[s ^ 1][lr + 64][sw], Q + (size_t)(bm + lr + 64) * DHh + k0 + lc * 4);
            cp16(&Ks[s ^ 1][lr][sw],      Kp + (size_t)(bn + lr) * DHh + k0 + lc * 4);
            cp16(&Ks[s ^ 1][lr + 64][sw], Kp + (size_t)(bn + lr + 64) * DHh + k0 + lc * 4);
            CP_COMMIT();
            CP_WAIT(1);
        } else {
            CP_WAIT(0);
        }
        __syncthreads();

#pragma unroll
        for (int k4 = 0; k4 < 4; k4++) {
            float4 a4[8], b4[8];
            const int sa = (k4 ^ (ty & 3)) * 4;
            const int sb = (k4 ^ (tx & 3)) * 4;
#pragma unroll
            for (int i = 0; i < 8; i++)
                a4[i] = *(const float4*)&Qs[s][ty * 8 + i][sa];
#pragma unroll
            for (int j = 0; j < 8; j++)
                b4[j] = *(const float4*)&Ks[s][tx * 8 + j][sb];
#pragma unroll
            for (int i = 0; i < 8; i++)
#pragma unroll
                for (int j = 0; j < 8; j++) {
                    float t = fmaf(a4[i].x, b4[j].x, acc[i][j]);
                    t = fmaf(a4[i].y, b4[j].y, t);
                    t = fmaf(a4[i].z, b4[j].z, t);
                    acc[i][j] = fmaf(a4[i].w, b4[j].w, t);
                }
        }
        __syncthreads();
    }

    float mk[8];
#pragma unroll
    for (int j = 0; j < 8; j++)
        mk[j] = mask[(size_t)b * Ss + bn + tx * 8 + j] * -1e9f;

#pragma unroll
    for (int i = 0; i < 8; i++) {
        const int row = ty * 8 + i;
        float e[8], rs = 0.f;
#pragma unroll
        for (int j = 0; j < 8; j++) {
            e[j] = __expf(acc[i][j] * 0.125f + mk[j]);
            rs += e[j];
        }
        float* dst = attn + ((size_t)bh * Ss + bm + row) * Ss + bn + tx * 8;
        *(float4*)(dst)     = make_float4(e[0], e[1], e[2], e[3]);
        *(float4*)(dst + 4) = make_float4(e[4], e[5], e[6], e[7]);
        red[row][tx] = rs;
    }
    __syncthreads();
    if (tid < 128) {
        float ssum = 0.f;
#pragma unroll
        for (int t = 0; t < 16; t++) ssum += red[tid][t];
        atomicAdd(&rowsum[(size_t)bh * Ss + bm + tid], ssum);
    }
}

// ---------------------------------------------------------------------------
// ctx: reads unnormalized e, scales by 1/rowsum, writes normalized attn back
// in-place, and computes ctx = attn_norm @ V into head-concat [B,S,D] layout.
// 128x64 tile, BK=16, 256 thr, 8x4/thread.
// ---------------------------------------------------------------------------
__global__ void __launch_bounds__(256)
ctx_k(float* __restrict__ attn, const float* __restrict__ Vh,
      const float* __restrict__ rowsum, float* __restrict__ ctx)
{
    const int bh = blockIdx.z;
    const int b  = bh >> 4;
    const int h  = bh & 15;
    float* A = attn + (size_t)bh * Ss * Ss;
    const float* V = Vh + (size_t)bh * Ss * DHh;
    const int bm = blockIdx.x * 128;

    __shared__ float As[2][128][16];
    __shared__ float Vs[2][16][64];

    const int tid = threadIdx.x;
    const int tx = tid & 15;
    const int ty = tid >> 4;

    const int lr = tid >> 2;
    const int lc = tid & 3;
    const int sw = (lc ^ ((lr >> 3) & 3)) * 4;
    const int vkr = tid >> 4;
    const int vc4 = (tid & 15) * 4;

    const float inv0 = 1.0f / rowsum[(size_t)bh * Ss + bm + lr];
    const float inv1 = 1.0f / rowsum[(size_t)bh * Ss + bm + lr + 64];

    float4 a0 = *(const float4*)(A + (size_t)(bm + lr) * Ss + lc * 4);
    float4 a1 = *(const float4*)(A + (size_t)(bm + lr + 64) * Ss + lc * 4);
    cp16(&Vs[0][vkr][vc4], V + (size_t)vkr * DHh + vc4);
    CP_COMMIT();

    float acc[8][4] = {};

    for (int it = 0; it < 128; ++it) {
        const int s = it & 1;
        // scale + publish to smem + write normalized attn back
        float4 p0 = make_float4(a0.x * inv0, a0.y * inv0, a0.z * inv0, a0.w * inv0);
        float4 p1 = make_float4(a1.x * inv1, a1.y * inv1, a1.z * inv1, a1.w * inv1);
        *(float4*)&As[s][lr][sw]      = p0;
        *(float4*)&As[s][lr + 64][sw] = p1;
        *(float4*)(A + (size_t)(bm + lr) * Ss + it * 16 + lc * 4)      = p0;
        *(float4*)(A + (size_t)(bm + lr + 64) * Ss + it * 16 + lc * 4) = p1;

        if (it + 1 < 128) {
            const int k0 = (it + 1) * 16;
            a0 = *(const float4*)(A + (size_t)(bm + lr) * Ss + k0 + lc * 4);
            a1 = *(const float4*)(A + (size_t)(bm + lr + 64) * Ss + k0 + lc * 4);
            cp16(&Vs[s ^ 1][vkr][vc4], V + (size_t)(k0 + vkr) * DHh + vc4);
            CP_COMMIT();
            CP_WAIT(1);
        } else {
            CP_WAIT(0);
        }
        __syncthreads();

#pragma unroll
        for (int k4 = 0; k4 < 4; k4++) {
            float4 a4[8];
            const int sa = (k4 ^ (ty & 3)) * 4;
#pragma unroll
            for (int i = 0; i < 8; i++)
                a4[i] = *(const float4*)&As[s][ty * 8 + i][sa];
#pragma unroll
            for (int kk = 0; kk < 4; kk++) {
                const float4 bv = *(const float4*)&Vs[s][k4 * 4 + kk][tx * 4];
#pragma unroll
                for (int i = 0; i < 8; i++) {
                    const float av = kk == 0 ? a4[i].x : kk == 1 ? a4[i].y
                                   : kk == 2 ? a4[i].z : a4[i].w;
                    acc[i][0] = fmaf(av, bv.x, acc[i][0]);
                    acc[i][1] = fmaf(av, bv.y, acc[i][1]);
                    acc[i][2] = fmaf(av, bv.z, acc[i][2]);
                    acc[i][3] = fmaf(av, bv.w, acc[i][3]);
                }
            }
        }
        __syncthreads();
    }

#pragma unroll
    for (int i = 0; i < 8; i++) {
        const int srow = bm + ty * 8 + i;
        float* dst = ctx + ((size_t)b * Ss + srow) * Dd + h * DHh + tx * 4;
        *(float4*)dst = make_float4(acc[i][0], acc[i][1], acc[i][2], acc[i][3]);
    }
}

// ---------------------------------------------------------------------------
extern "C" void kernel_launch(void* const* d_in, const int* in_sizes, int n_in,
                              void* d_out, int out_size)
{
    const float* q    = (const float*)d_in[0];
    const float* k    = (const float*)d_in[1];
    const float* v    = (const float*)d_in[2];
    const float* mask = (const float*)d_in[3];
    const float* Wq   = (const float*)d_in[4];
    const float* bq   = (const float*)d_in[5];
    const float* Wk   = (const float*)d_in[6];
    const float* bk   = (const float*)d_in[7];
    const float* Wv   = (const float*)d_in[8];
    const float* bv   = (const float*)d_in[9];
    const float* Wo   = (const float*)d_in[10];
    const float* bo   = (const float*)d_in[11];

    float* out  = (float*)d_out;
    float* attn = out + (size_t)BSz * Dd;

    float *Qh, *Kh, *Vh, *ctx, *rowsum;
    cudaGetSymbolAddress((void**)&Qh,     g_Qh);
    cudaGetSymbolAddress((void**)&Kh,     g_Kh);
    cudaGetSymbolAddress((void**)&Vh,     g_Vh);
    cudaGetSymbolAddress((void**)&ctx,    g_ctx);
    cudaGetSymbolAddress((void**)&rowsum, g_rowsum);

    zero_k<<<(BH * Ss) / 256, 256>>>(rowsum, BH * Ss);

    gemm_k<1><<<dim3(8, 64, 3), 256>>>(q, k, v, Wq, Wk, Wv, bq, bk, bv,
                                       Qh, Kh, Vh);

    logits_k<<<dim3(16, 16, 64), 256>>>(Qh, Kh, mask, attn, rowsum);

    ctx_k<<<dim3(16, 1, 64), 256>>>(attn, Vh, rowsum, ctx);

    gemm_k<0><<<dim3(8, 64, 1), 256>>>(ctx, ctx, ctx, Wo, Wo, Wo, bo, bo, bo,
                                       out, out, out);
}

// round 3
// speedup vs baseline: 1.8000x; 1.6843x over previous
#include <cuda_runtime.h>
#include <cuda_bf16.h>
#include <cstdint>

#define Ss  2048
#define Dd  1024
#define Hh  16
#define BH  64
#define BSz 8192

// Scratch (__device__ globals; no allocation)
__device__ __nv_bfloat16 g_Qhi[(size_t)BH * Ss * 64];
__device__ __nv_bfloat16 g_Qlo[(size_t)BH * Ss * 64];
__device__ __nv_bfloat16 g_Khi[(size_t)BH * Ss * 64];
__device__ __nv_bfloat16 g_Klo[(size_t)BH * Ss * 64];
__device__ __nv_bfloat16 g_Vhi[(size_t)BH * Ss * 64];
__device__ __nv_bfloat16 g_Vlo[(size_t)BH * Ss * 64];
__device__ float g_ctx[(size_t)BSz * Dd];
__device__ float g_rowsum[(size_t)BH * Ss];

// ---------------------------------------------------------------------------
__device__ __forceinline__ void cp16(void* dst, const void* src) {
    uint32_t d;
    asm volatile("{ .reg .u64 t; cvta.to.shared.u64 t, %1; cvt.u32.u64 %0, t; }"
                 : "=r"(d) : "l"(dst));
    asm volatile("cp.async.cg.shared.global [%0], [%1], 16;" :: "r"(d), "l"(src));
}
#define CP_COMMIT() asm volatile("cp.async.commit_group;")
#define CP_WAIT(n)  asm volatile("cp.async.wait_group %0;" :: "n"(n))

__device__ __forceinline__ uint32_t pack_bf2(__nv_bfloat16 a, __nv_bfloat16 b) {
    return (uint32_t)__bfloat16_as_ushort(a) | ((uint32_t)__bfloat16_as_ushort(b) << 16);
}
__device__ __forceinline__ void split1(float x, __nv_bfloat16& h, __nv_bfloat16& l) {
    h = __float2bfloat16(x);
    l = __float2bfloat16(x - __bfloat162float(h));
}
__device__ __forceinline__ void mma_bf16(float c[4], const uint32_t a[4], const uint32_t b[2]) {
    asm volatile(
        "mma.sync.aligned.m16n8k16.row.col.f32.bf16.bf16.f32 "
        "{%0,%1,%2,%3}, {%4,%5,%6,%7}, {%8,%9}, {%0,%1,%2,%3};"
        : "+f"(c[0]), "+f"(c[1]), "+f"(c[2]), "+f"(c[3])
        : "r"(a[0]), "r"(a[1]), "r"(a[2]), "r"(a[3]), "r"(b[0]), "r"(b[1]));
}

__global__ void zero_k(float* p, int n) {
    int i = blockIdx.x * 256 + threadIdx.x;
    if (i < n) p[i] = 0.f;
}

// ---------------------------------------------------------------------------
// proj_k: Y = X[8192,1024] @ W[1024,1024] + bias.  z selects matrix set.
// DENSE=0: write bf16 hi/lo pairs in head-split layout. DENSE=1: fp32 [M,N].
// 512 thr, CTA 128x128, warp 32x32 (mt2 x nt4), BK=16, double-buffered smem.
// ---------------------------------------------------------------------------
template <int DENSE>
__global__ void __launch_bounds__(512, 1)
proj_k(const float* __restrict__ X0, const float* __restrict__ X1,
       const float* __restrict__ X2,
       const float* __restrict__ W0, const float* __restrict__ W1,
       const float* __restrict__ W2,
       const float* __restrict__ B0, const float* __restrict__ B1,
       const float* __restrict__ B2,
       __nv_bfloat16* __restrict__ H0, __nv_bfloat16* __restrict__ L0,
       __nv_bfloat16* __restrict__ H1, __nv_bfloat16* __restrict__ L1,
       __nv_bfloat16* __restrict__ H2, __nv_bfloat16* __restrict__ L2,
       float* __restrict__ OUT)
{
    const int z = blockIdx.z;
    const float* X  = z == 0 ? X0 : z == 1 ? X1 : X2;
    const float* W  = z == 0 ? W0 : z == 1 ? W1 : W2;
    const float* Bi = z == 0 ? B0 : z == 1 ? B1 : B2;
    __nv_bfloat16* Hd = z == 0 ? H0 : z == 1 ? H1 : H2;
    __nv_bfloat16* Ld = z == 0 ? L0 : z == 1 ? L1 : L2;

    __shared__ __nv_bfloat16 As[2][2][128][24];
    __shared__ __nv_bfloat16 Bs[2][2][16][136];

    const int tid = threadIdx.x, lane = tid & 31, warp = tid >> 5;
    const int g = lane >> 2, t = lane & 3;
    const int wm = warp >> 2, wn = warp & 3;
    const int bm = blockIdx.y * 128, bn = blockIdx.x * 128;

    const int ar = tid >> 2, ac = tid & 3;
    const int br = tid >> 5, bc = (tid & 31) * 4;

    float acc[2][4][4] = {};

    float4 ax = *(const float4*)(X + (size_t)(bm + ar) * 1024 + ac * 4);
    float4 bx = *(const float4*)(W + (size_t)br * 1024 + bn + bc);

    for (int it = 0; it < 64; ++it) {
        const int s = it & 1;
        {
            __nv_bfloat16 h0, h1, h2, h3, l0, l1, l2, l3;
            split1(ax.x, h0, l0); split1(ax.y, h1, l1);
            split1(ax.z, h2, l2); split1(ax.w, h3, l3);
            *(uint2*)&As[s][0][ar][ac * 4] = make_uint2(pack_bf2(h0, h1), pack_bf2(h2, h3));
            *(uint2*)&As[s][1][ar][ac * 4] = make_uint2(pack_bf2(l0, l1), pack_bf2(l2, l3));
            split1(bx.x, h0, l0); split1(bx.y, h1, l1);
            split1(bx.z, h2, l2); split1(bx.w, h3, l3);
            *(uint2*)&Bs[s][0][br][bc] = make_uint2(pack_bf2(h0, h1), pack_bf2(h2, h3));
            *(uint2*)&Bs[s][1][br][bc] = make_uint2(pack_bf2(l0, l1), pack_bf2(l2, l3));
        }
        if (it + 1 < 64) {
            const int k0 = (it + 1) * 16;
            ax = *(const float4*)(X + (size_t)(bm + ar) * 1024 + k0 + ac * 4);
            bx = *(const float4*)(W + (size_t)(k0 + br) * 1024 + bn + bc);
        }
        __syncthreads();

        const __nv_bfloat16* Ah = &As[s][0][0][0];
        const __nv_bfloat16* Al = &As[s][1][0][0];
        uint32_t af[2][2][4];
#pragma unroll
        for (int mt = 0; mt < 2; mt++) {
            const int r = wm * 32 + mt * 16;
#pragma unroll
            for (int hl = 0; hl < 2; hl++) {
                const __nv_bfloat16* P = hl ? Al : Ah;
                af[mt][hl][0] = *(const uint32_t*)(P + (r + g) * 24 + 2 * t);
                af[mt][hl][1] = *(const uint32_t*)(P + (r + g + 8) * 24 + 2 * t);
                af[mt][hl][2] = *(const uint32_t*)(P + (r + g) * 24 + 2 * t + 8);
                af[mt][hl][3] = *(const uint32_t*)(P + (r + g + 8) * 24 + 2 * t + 8);
            }
        }
        const unsigned short* Bh = (const unsigned short*)&Bs[s][0][0][0];
        const unsigned short* Bl = (const unsigned short*)&Bs[s][1][0][0];
        uint32_t bfr[4][2][2];
#pragma unroll
        for (int nt = 0; nt < 4; nt++) {
            const int n = wn * 32 + nt * 8 + g;
#pragma unroll
            for (int hl = 0; hl < 2; hl++) {
                const unsigned short* P = hl ? Bl : Bh;
                bfr[nt][hl][0] = (uint32_t)P[(2 * t) * 136 + n] |
                                 ((uint32_t)P[(2 * t + 1) * 136 + n] << 16);
                bfr[nt][hl][1] = (uint32_t)P[(2 * t + 8) * 136 + n] |
                                 ((uint32_t)P[(2 * t + 9) * 136 + n] << 16);
            }
        }
#pragma unroll
        for (int mt = 0; mt < 2; mt++)
#pragma unroll
            for (int nt = 0; nt < 4; nt++) {
                mma_bf16(acc[mt][nt], af[mt][0], bfr[nt][0]);
                mma_bf16(acc[mt][nt], af[mt][0], bfr[nt][1]);
                mma_bf16(acc[mt][nt], af[mt][1], bfr[nt][0]);
            }
    }

#pragma unroll
    for (int mt = 0; mt < 2; mt++) {
        const int row0 = bm + wm * 32 + mt * 16 + g;
#pragma unroll
        for (int nt = 0; nt < 4; nt++) {
            const int col = bn + wn * 32 + nt * 8 + 2 * t;
            const float b0 = Bi[col], b1 = Bi[col + 1];
            const float v00 = acc[mt][nt][0] + b0, v01 = acc[mt][nt][1] + b1;
            const float v10 = acc[mt][nt][2] + b0, v11 = acc[mt][nt][3] + b1;
            if (DENSE) {
                *(float2*)(OUT + (size_t)row0 * 1024 + col)       = make_float2(v00, v01);
                *(float2*)(OUT + (size_t)(row0 + 8) * 1024 + col) = make_float2(v10, v11);
            } else {
                const int hh = col >> 6, dc = col & 63;
                const int b_ = row0 >> 11;
                const size_t o0 = (((size_t)b_ * 16 + hh) * 2048 + (row0 & 2047)) * 64 + dc;
                const size_t o1 = (((size_t)b_ * 16 + hh) * 2048 + ((row0 + 8) & 2047)) * 64 + dc;
                __nv_bfloat16 h0, l0, h1, l1;
                split1(v00, h0, l0); split1(v01, h1, l1);
                *(uint32_t*)&Hd[o0] = pack_bf2(h0, h1);
                *(uint32_t*)&Ld[o0] = pack_bf2(l0, l1);
                split1(v10, h0, l0); split1(v11, h1, l1);
                *(uint32_t*)&Hd[o1] = pack_bf2(h0, h1);
                *(uint32_t*)&Ld[o1] = pack_bf2(l0, l1);
            }
        }
    }
}

// ---------------------------------------------------------------------------
// logits_k: e = exp(0.125 * Q K^T + mask*-1e9); rowsum += partials.
// 512 thr, CTA 128x128 per bh, full K=64 staged once via cp.async (bf16 hi/lo).
// ---------------------------------------------------------------------------
__global__ void __launch_bounds__(512, 1)
logits_k(const __nv_bfloat16* __restrict__ Qhi, const __nv_bfloat16* __restrict__ Qlo,
         const __nv_bfloat16* __restrict__ Khi, const __nv_bfloat16* __restrict__ Klo,
         const float* __restrict__ mask, float* __restrict__ attn,
         float* __restrict__ rowsum)
{
    extern __shared__ __nv_bfloat16 dyn[];
    __shared__ float red[128];

    const int bh = blockIdx.z, b = bh >> 4;
    const int bm = blockIdx.y * 128, bn = blockIdx.x * 128;
    const int tid = threadIdx.x, lane = tid & 31, warp = tid >> 5;
    const int g = lane >> 2, t = lane & 3;
    const int wm = warp >> 2, wn = warp & 3;

    if (tid < 128) red[tid] = 0.f;

#pragma unroll
    for (int j = 0; j < 8; j++) {
        const int id = j * 512 + tid;
        const int p = id >> 10, r = (id >> 3) & 127, ch = id & 7;
        const __nv_bfloat16* src =
            p == 0 ? Qhi + ((size_t)bh * 2048 + bm + r) * 64 + ch * 8 :
            p == 1 ? Qlo + ((size_t)bh * 2048 + bm + r) * 64 + ch * 8 :
            p == 2 ? Khi + ((size_t)bh * 2048 + bn + r) * 64 + ch * 8 :
                     Klo + ((size_t)bh * 2048 + bn + r) * 64 + ch * 8;
        cp16(dyn + p * 9216 + r * 72 + ch * 8, src);
    }
    CP_COMMIT(); CP_WAIT(0);
    __syncthreads();

    const __nv_bfloat16* Qh_ = dyn;
    const __nv_bfloat16* Ql_ = dyn + 9216;
    const __nv_bfloat16* Kh_ = dyn + 18432;
    const __nv_bfloat16* Kl_ = dyn + 27648;

    float acc[2][4][4] = {};
#pragma unroll
    for (int kc = 0; kc < 64; kc += 16) {
        uint32_t af[2][2][4];
#pragma unroll
        for (int mt = 0; mt < 2; mt++) {
            const int r = wm * 32 + mt * 16;
#pragma unroll
            for (int hl = 0; hl < 2; hl++) {
                const __nv_bfloat16* P = hl ? Ql_ : Qh_;
                af[mt][hl][0] = *(const uint32_t*)(P + (r + g) * 72 + kc + 2 * t);
                af[mt][hl][1] = *(const uint32_t*)(P + (r + g + 8) * 72 + kc + 2 * t);
                af[mt][hl][2] = *(const uint32_t*)(P + (r + g) * 72 + kc + 2 * t + 8);
                af[mt][hl][3] = *(const uint32_t*)(P + (r + g + 8) * 72 + kc + 2 * t + 8);
            }
        }
        uint32_t bfr[4][2][2];
#pragma unroll
        for (int nt = 0; nt < 4; nt++) {
            const int n = wn * 32 + nt * 8 + g;
#pragma unroll
            for (int hl = 0; hl < 2; hl++) {
                const __nv_bfloat16* P = hl ? Kl_ : Kh_;
                bfr[nt][hl][0] = *(const uint32_t*)(P + n * 72 + kc + 2 * t);
                bfr[nt][hl][1] = *(const uint32_t*)(P + n * 72 + kc + 2 * t + 8);
            }
        }
#pragma unroll
        for (int mt = 0; mt < 2; mt++)
#pragma unroll
            for (int nt = 0; nt < 4; nt++) {
                mma_bf16(acc[mt][nt], af[mt][0], bfr[nt][0]);
                mma_bf16(acc[mt][nt], af[mt][0], bfr[nt][1]);
                mma_bf16(acc[mt][nt], af[mt][1], bfr[nt][0]);
            }
    }

    float rs[2][2] = {};
#pragma unroll
    for (int mt = 0; mt < 2; mt++) {
        const int rl0 = wm * 32 + mt * 16 + g;
#pragma unroll
        for (int nt = 0; nt < 4; nt++) {
            const int cl = wn * 32 + nt * 8 + 2 * t;
            const int gc = bn + cl;
            const float mk0 = mask[(size_t)b * 2048 + gc] * -1e9f;
            const float mk1 = mask[(size_t)b * 2048 + gc + 1] * -1e9f;
            const float e00 = __expf(acc[mt][nt][0] * 0.125f + mk0);
            const float e01 = __expf(acc[mt][nt][1] * 0.125f + mk1);
            const float e10 = __expf(acc[mt][nt][2] * 0.125f + mk0);
            const float e11 = __expf(acc[mt][nt][3] * 0.125f + mk1);
            *(float2*)(attn + ((size_t)bh * 2048 + bm + rl0) * 2048 + gc)     = make_float2(e00, e01);
            *(float2*)(attn + ((size_t)bh * 2048 + bm + rl0 + 8) * 2048 + gc) = make_float2(e10, e11);
            rs[mt][0] += e00 + e01;
            rs[mt][1] += e10 + e11;
        }
    }
#pragma unroll
    for (int mt = 0; mt < 2; mt++)
#pragma unroll
        for (int hf = 0; hf < 2; hf++) {
            float v = rs[mt][hf];
            v += __shfl_xor_sync(0xffffffffu, v, 1);
            v += __shfl_xor_sync(0xffffffffu, v, 2);
            if (t == 0) atomicAdd(&red[wm * 32 + mt * 16 + hf * 8 + g], v);
        }
    __syncthreads();
    if (tid < 128) atomicAdd(&rowsum[(size_t)bh * 2048 + bm + tid], red[tid]);
}

// ---------------------------------------------------------------------------
// ctx_k: normalize attn in-place (fp32) + ctx = P @ V (split-bf16 MMA).
// 256 thr, CTA 128x64 per bh, BK=16 double-buffered.
// ---------------------------------------------------------------------------
__global__ void __launch_bounds__(256, 2)
ctx_k(float* __restrict__ attn,
      const __nv_bfloat16* __restrict__ Vhi, const __nv_bfloat16* __restrict__ Vlo,
      const float* __restrict__ rowsum, float* __restrict__ ctx)
{
    __shared__ __nv_bfloat16 As[2][2][128][24];
    __shared__ __nv_bfloat16 Vs[2][2][16][72];

    const int bh = blockIdx.z, b = bh >> 4, h = bh & 15;
    float* A = attn + (size_t)bh * 2048 * 2048;
    const int bm = blockIdx.x * 128;
    const int tid = threadIdx.x, lane = tid & 31, warp = tid >> 5;
    const int g = lane >> 2, t = lane & 3;
    const int wm = warp >> 1, wn = warp & 1;

    const int lr = tid >> 2, lc = tid & 3;
    const float inv0 = 1.f / rowsum[(size_t)bh * 2048 + bm + lr];
    const float inv1 = 1.f / rowsum[(size_t)bh * 2048 + bm + lr + 64];

    const int vp = tid >> 7, vid = tid & 127, vkr = vid >> 3, vch = vid & 7;
    const __nv_bfloat16* Vsrc = vp ? Vlo : Vhi;

    float4 a0 = *(const float4*)(A + (size_t)(bm + lr) * 2048 + lc * 4);
    float4 a1 = *(const float4*)(A + (size_t)(bm + lr + 64) * 2048 + lc * 4);
    cp16(&Vs[0][vp][vkr][vch * 8], Vsrc + ((size_t)bh * 2048 + vkr) * 64 + vch * 8);
    CP_COMMIT();

    float acc[2][4][4] = {};

    for (int it = 0; it < 128; ++it) {
        const int s = it & 1;
        const float4 p0 = make_float4(a0.x * inv0, a0.y * inv0, a0.z * inv0, a0.w * inv0);
        const float4 p1 = make_float4(a1.x * inv1, a1.y * inv1, a1.z * inv1, a1.w * inv1);
        *(float4*)(A + (size_t)(bm + lr) * 2048 + it * 16 + lc * 4)      = p0;
        *(float4*)(A + (size_t)(bm + lr + 64) * 2048 + it * 16 + lc * 4) = p1;
        {
            __nv_bfloat16 h0, h1, h2, h3, l0, l1, l2, l3;
            split1(p0.x, h0, l0); split1(p0.y, h1, l1);
            split1(p0.z, h2, l2); split1(p0.w, h3, l3);
            *(uint2*)&As[s][0][lr][lc * 4] = make_uint2(pack_bf2(h0, h1), pack_bf2(h2, h3));
            *(uint2*)&As[s][1][lr][lc * 4] = make_uint2(pack_bf2(l0, l1), pack_bf2(l2, l3));
            split1(p1.x, h0, l0); split1(p1.y, h1, l1);
            split1(p1.z, h2, l2); split1(p1.w, h3, l3);
            *(uint2*)&As[s][0][lr + 64][lc * 4] = make_uint2(pack_bf2(h0, h1), pack_bf2(h2, h3));
            *(uint2*)&As[s][1][lr + 64][lc * 4] = make_uint2(pack_bf2(l0, l1), pack_bf2(l2, l3));
        }
        if (it + 1 < 128) {
            const int k0 = (it + 1) * 16;
            a0 = *(const float4*)(A + (size_t)(bm + lr) * 2048 + k0 + lc * 4);
            a1 = *(const float4*)(A + (size_t)(bm + lr + 64) * 2048 + k0 + lc * 4);
        }
        CP_WAIT(0);
        __syncthreads();
        if (it + 1 < 128) {
            const int k0 = (it + 1) * 16;
            cp16(&Vs[s ^ 1][vp][vkr][vch * 8],
                 Vsrc + ((size_t)bh * 2048 + k0 + vkr) * 64 + vch * 8);
            CP_COMMIT();
        }

        const __nv_bfloat16* Ah = &As[s][0][0][0];
        const __nv_bfloat16* Al = &As[s][1][0][0];
        uint32_t af[2][2][4];
#pragma unroll
        for (int mt = 0; mt < 2; mt++) {
            const int r = wm * 32 + mt * 16;
#pragma unroll
            for (int hl = 0; hl < 2; hl++) {
                const __nv_bfloat16* P = hl ? Al : Ah;
                af[mt][hl][0] = *(const uint32_t*)(P + (r + g) * 24 + 2 * t);
                af[mt][hl][1] = *(const uint32_t*)(P + (r + g + 8) * 24 + 2 * t);
                af[mt][hl][2] = *(const uint32_t*)(P + (r + g) * 24 + 2 * t + 8);
                af[mt][hl][3] = *(const uint32_t*)(P + (r + g + 8) * 24 + 2 * t + 8);
            }
        }
        const unsigned short* Bh_ = (const unsigned short*)&Vs[s][0][0][0];
        const unsigned short* Bl_ = (const unsigned short*)&Vs[s][1][0][0];
        uint32_t bfr[4][2][2];
#pragma unroll
        for (int nt = 0; nt < 4; nt++) {
            const int n = wn * 32 + nt * 8 + g;
#pragma unroll
            for (int hl = 0; hl < 2; hl++) {
                const unsigned short* P = hl ? Bl_ : Bh_;
                bfr[nt][hl][0] = (uint32_t)P[(2 * t) * 72 + n] |
                                 ((uint32_t)P[(2 * t + 1) * 72 + n] << 16);
                bfr[nt][hl][1] = (uint32_t)P[(2 * t + 8) * 72 + n] |
                                 ((uint32_t)P[(2 * t + 9) * 72 + n] << 16);
            }
        }
#pragma unroll
        for (int mt = 0; mt < 2; mt++)
#pragma unroll
            for (int nt = 0; nt < 4; nt++) {
                mma_bf16(acc[mt][nt], af[mt][0], bfr[nt][0]);
                mma_bf16(acc[mt][nt], af[mt][0], bfr[nt][1]);
                mma_bf16(acc[mt][nt], af[mt][1], bfr[nt][0]);
            }
    }

#pragma unroll
    for (int mt = 0; mt < 2; mt++) {
        const int row0 = bm + wm * 32 + mt * 16 + g;
#pragma unroll
        for (int nt = 0; nt < 4; nt++) {
            const int col = wn * 32 + nt * 8 + 2 * t;
            *(float2*)(ctx + ((size_t)b * 2048 + row0) * 1024 + h * 64 + col) =
                make_float2(acc[mt][nt][0], acc[mt][nt][1]);
            *(float2*)(ctx + ((size_t)b * 2048 + row0 + 8) * 1024 + h * 64 + col) =
                make_float2(acc[mt][nt][2], acc[mt][nt][3]);
        }
    }
}

// ---------------------------------------------------------------------------
extern "C" void kernel_launch(void* const* d_in, const int* in_sizes, int n_in,
                              void* d_out, int out_size)
{
    const float* q    = (const float*)d_in[0];
    const float* k    = (const float*)d_in[1];
    const float* v    = (const float*)d_in[2];
    const float* mask = (const float*)d_in[3];
    const float* Wq   = (const float*)d_in[4];
    const float* bq   = (const float*)d_in[5];
    const float* Wk   = (const float*)d_in[6];
    const float* bk   = (const float*)d_in[7];
    const float* Wv   = (const float*)d_in[8];
    const float* bv   = (const float*)d_in[9];
    const float* Wo   = (const float*)d_in[10];
    const float* bo   = (const float*)d_in[11];

    float* out  = (float*)d_out;
    float* attn = out + (size_t)BSz * Dd;

    __nv_bfloat16 *Qhi, *Qlo, *Khi, *Klo, *Vhi, *Vlo;
    float *ctxp, *rowsum;
    cudaGetSymbolAddress((void**)&Qhi, g_Qhi);
    cudaGetSymbolAddress((void**)&Qlo, g_Qlo);
    cudaGetSymbolAddress((void**)&Khi, g_Khi);
    cudaGetSymbolAddress((void**)&Klo, g_Klo);
    cudaGetSymbolAddress((void**)&Vhi, g_Vhi);
    cudaGetSymbolAddress((void**)&Vlo, g_Vlo);
    cudaGetSymbolAddress((void**)&ctxp, g_ctx);
    cudaGetSymbolAddress((void**)&rowsum, g_rowsum);

    cudaFuncSetAttribute(logits_k, cudaFuncAttributeMaxDynamicSharedMemorySize, 73728);

    zero_k<<<512, 256>>>(rowsum, BH * Ss);

    proj_k<0><<<dim3(8, 64, 3), 512>>>(q, k, v, Wq, Wk, Wv, bq, bk, bv,
                                       Qhi, Qlo, Khi, Klo, Vhi, Vlo, nullptr);

    logits_k<<<dim3(16, 16, 64), 512, 73728>>>(Qhi, Qlo, Khi, Klo, mask, attn, rowsum);

    ctx_k<<<dim3(16, 1, 64), 256>>>(attn, Vhi, Vlo, rowsum, ctxp);

    proj_k<1><<<dim3(8, 64, 1), 512>>>(ctxp, ctxp, ctxp, Wo, Wo, Wo, bo, bo, bo,
                                       nullptr, nullptr, nullptr, nullptr,
                                       nullptr, nullptr, out);
}